// round 11
// baseline (speedup 1.0000x reference)
#include <cuda_runtime.h>
#include <cuda_bf16.h>
#include <cstdint>

// ChempropBlock: V=10000 nodes, E=160000 edges, D=512, DEPTH=3
// out = [node_hiddens (V*D) | eh (E*D)] fp32
//
// Per layer l:
//   nm_cur = segment_sum(relu(eh), dest)   (produced by previous epilogue / init)
//   ehout  = ehin + (nm_cur[src] - relu(ehin[rev])) @ W[l]^T + b[l]
//   epilogue scatters relu(ehout) into nm_next (plain into out_nodes last layer).
// GEMM: mma.sync m16n8k16 bf16, 3-term split (D += A0B0 + A1B0 + A0B1).
// R11: eh gathers (DRAM) pipelined 2 chunks ahead (double raw buffer,
// wait_group<=1); nm gathers (L2-resident) prefetched 1 ahead in registers;
// 3 nm buffers + fused upfront zeroing (fewer launches, ncu lands on GEMM).

#define V_N 10000
#define E_N 160000
#define D_N 512
#define DEPTH_N 3

#define TM 128
#define TN 128
#define KC 32
#define NCHUNK (D_N / KC)     // 16

__device__ float g_nm0[(size_t)V_N * D_N];
__device__ float g_nm1[(size_t)V_N * D_N];
__device__ float g_nm2[(size_t)V_N * D_N];
__device__ float g_eh[(size_t)E_N * D_N];
// W fragments: [layer(3)][nblock(4)][chunk(16)][k16(2)][nb(16)][lane(32)] uint4
__device__ uint4 g_wfrag[3 * 4 * 16 * 2 * 16 * 32];

__device__ __forceinline__ uint32_t smem_u32(const void* p) {
    uint32_t a;
    asm("{ .reg .u64 t; cvta.to.shared.u64 t, %1; cvt.u32.u64 %0, t; }"
        : "=r"(a) : "l"(p));
    return a;
}
__device__ __forceinline__ uint32_t pack_bf2(float x, float y, float2& back) {
    __nv_bfloat162 h = __float22bfloat162_rn(make_float2(x, y));
    back = __bfloat1622float2(h);
    return *(uint32_t*)&h;
}
__device__ __forceinline__ uint32_t pack_bf2n(float x, float y) {
    __nv_bfloat162 h = __float22bfloat162_rn(make_float2(x, y));
    return *(uint32_t*)&h;
}
__device__ __forceinline__ void red_add_v4(float* addr, float4 v) {
    asm volatile("red.global.add.v4.f32 [%0], {%1, %2, %3, %4};"
                 :: "l"(addr), "f"(v.x), "f"(v.y), "f"(v.z), "f"(v.w)
                 : "memory");
}
__device__ __forceinline__ void red_add_v2(float* addr, float x, float y) {
    asm volatile("red.global.add.v2.f32 [%0], {%1, %2};"
                 :: "l"(addr), "f"(x), "f"(y)
                 : "memory");
}
__device__ __forceinline__ void ldmatrix_x4(uint32_t* r, uint32_t addr) {
    asm volatile("ldmatrix.sync.aligned.m8n8.x4.shared.b16 {%0,%1,%2,%3}, [%4];"
                 : "=r"(r[0]), "=r"(r[1]), "=r"(r[2]), "=r"(r[3])
                 : "r"(addr));
}

__device__ __forceinline__ void mma_bf16(float* d, const uint32_t* a,
                                         uint32_t b0, uint32_t b1) {
    asm volatile(
        "mma.sync.aligned.m16n8k16.row.col.f32.bf16.bf16.f32 "
        "{%0,%1,%2,%3}, {%4,%5,%6,%7}, {%8,%9}, {%0,%1,%2,%3};"
        : "+f"(d[0]), "+f"(d[1]), "+f"(d[2]), "+f"(d[3])
        : "r"(a[0]), "r"(a[1]), "r"(a[2]), "r"(a[3]), "r"(b0), "r"(b1));
}

#define CP_ASYNC_16(dst_u32, src_ptr) \
    asm volatile("cp.async.cg.shared.global [%0], [%1], 16;" \
                 :: "r"(dst_u32), "l"(src_ptr) : "memory")
#define CP_ASYNC_COMMIT() asm volatile("cp.async.commit_group;" ::: "memory")
#define CP_ASYNC_WAIT0()  asm volatile("cp.async.wait_group 0;" ::: "memory")
#define CP_ASYNC_WAIT1()  asm volatile("cp.async.wait_group 1;" ::: "memory")

// ---------------------------------------------------------------------------
// zero nm0, nm1, nm2, out_nodes in one launch (grid = 4 * V*D/4 / 256)
__global__ void k_zero_all(float4* __restrict__ a, float4* __restrict__ b,
                           float4* __restrict__ c, float4* __restrict__ d) {
    const int n4 = V_N * D_N / 4;
    int i = blockIdx.x * blockDim.x + threadIdx.x;
    int which = i / n4;
    int off = i - which * n4;
    float4* p = (which == 0) ? a : (which == 1) ? b : (which == 2) ? c : d;
    p[off] = make_float4(0.f, 0.f, 0.f, 0.f);
}

// eh0 = nf[src] + ef ; relu-scatter eh0 into nm
__global__ void k_init_eh_scatter(const float* __restrict__ nf,
                                  const float* __restrict__ ef,
                                  const int* __restrict__ src,
                                  const int* __restrict__ dst,
                                  float* __restrict__ nm) {
    int idx = blockIdx.x * blockDim.x + threadIdx.x;   // < E*D/4
    int e = idx >> 7;
    int c = (idx & 127) << 2;
    int s = __ldg(&src[e]);
    const float4 a = *(const float4*)(nf + (size_t)s * D_N + c);
    const float4 b = *(const float4*)(ef + (size_t)e * D_N + c);
    float4 r; r.x = a.x + b.x; r.y = a.y + b.y; r.z = a.z + b.z; r.w = a.w + b.w;
    *(float4*)(g_eh + (size_t)e * D_N + c) = r;
    int d = __ldg(&dst[e]);
    float4 rr;
    rr.x = fmaxf(r.x, 0.f); rr.y = fmaxf(r.y, 0.f);
    rr.z = fmaxf(r.z, 0.f); rr.w = fmaxf(r.w, 0.f);
    red_add_v4(nm + (size_t)d * D_N + c, rr);
}

// Precompute bf16-split W fragments (m16n8k16 B operand layout, row.col).
__global__ void k_wfrag(const float* __restrict__ Ws) {
    int t = blockIdx.x * blockDim.x + threadIdx.x;     // < 196608
    int lane  = t & 31;
    int nb    = (t >> 5) & 15;
    int k16   = (t >> 9) & 1;
    int chunk = (t >> 10) & 15;
    int nblk  = (t >> 14) & 3;
    int layer = t >> 16;
    int n = nblk * 128 + nb * 8 + (lane >> 2);
    int k = chunk * 32 + k16 * 16 + (lane & 3) * 2;
    const float* w = Ws + ((size_t)layer * D_N + n) * D_N + k;
    float w00 = w[0], w01 = w[1], w10 = w[8], w11 = w[9];
    float2 bk;
    uint4 o;
    o.x = pack_bf2(w00, w01, bk);
    o.z = pack_bf2n(w00 - bk.x, w01 - bk.y);
    o.y = pack_bf2(w10, w11, bk);
    o.w = pack_bf2n(w10 - bk.x, w11 - bk.y);
    g_wfrag[t] = o;
}

// ---------------------------------------------------------------------------
// GEMM smem (b32 units):
//   [0..511]       s_src/s_rev/s_dst (128 ints each) + pad
//   RAWE(s) = 512 + s*4096 : raw eh rows, 2 stages (128 rows x 32 b32,
//                  16B-granule swizzle g ^= row&7)
//   SA(st,sp) = 8704 + st*4096 + sp*2048 : bf16 A split tiles,
//                  [row][16 b32], 4B-idx swizzle: phys = idx ^ (((row>>1)&3)<<2)
//   SB(st)   = 16896 + st*4096 : W fragments [k16][nb][lane] uint4
// total 25088 b32 = 100352 B -> 2 CTA/SM
// ---------------------------------------------------------------------------
#define RAWE(s)      (512 + (s) * 4096)
#define SA_O(st, sp) (8704 + (st) * 4096 + (sp) * 2048)
#define SB_O(st)     (16896 + (st) * 4096)
#define SMEM_U32 25088

__global__ void __launch_bounds__(256, 2)
k_gemm_mma(const uint4* __restrict__ wf,       // this layer's fragment table
           const float* __restrict__ bias,
           const float* __restrict__ nm,
           const float* __restrict__ ehin,
           float* __restrict__ ehout,
           const int* __restrict__ src,
           const int* __restrict__ rev,
           const int* __restrict__ dst,
           float* __restrict__ scat,
           int do_relu) {
    extern __shared__ float smemf[];
    uint32_t* smemu = (uint32_t*)smemf;
    int* s_src = (int*)smemf;
    int* s_rev = (int*)smemf + 128;
    int* s_dst = (int*)smemf + 256;

    const int tid = threadIdx.x;
    const int wid = tid >> 5;
    const int lid = tid & 31;
    const int mBase = blockIdx.y * TM;
    const int nBase = blockIdx.x * TN;
    const uint4* wfn = wf + (size_t)blockIdx.x * (NCHUNK * 1024); // 1024 uint4/chunk

    if (tid < TM) {
        s_src[tid] = __ldg(&src[mBase + tid]);
        s_rev[tid] = __ldg(&rev[mBase + tid]);
        s_dst[tid] = __ldg(&dst[mBase + tid]);
    }
    __syncthreads();

    const uint32_t sb = smem_u32(smemf);

    // staging coords: 8 threads per row, 16B each, 4 row-passes
    const int strow0 = tid >> 3;      // 0..31
    const int kp     = tid & 7;       // 16B granule in 128B row

    uint32_t rawDstE[4];              // stage-0 dst; stage 1 adds 4096*4 bytes
    const float* gsrcN[4];
    const float* gsrcE[4];
#pragma unroll
    for (int p = 0; p < 4; ++p) {
        const int row = strow0 + 32 * p;
        const int g = kp ^ (row & 7);
        rawDstE[p] = sb + (RAWE(0) + row * 32 + g * 4) * 4;
        gsrcN[p] = nm + (size_t)s_src[row] * D_N + kp * 4;
        gsrcE[p] = ehin + (size_t)s_rev[row] * D_N + kp * 4;
    }

    // eh gathers -> raw smem stage s (cp.async, DRAM-latency tolerant, 2-ahead)
    auto issue_eh = [&](int c, int s) {
        const int ko = c * KC;
        const uint32_t add = (uint32_t)s * (4096 * 4);
#pragma unroll
        for (int p = 0; p < 4; ++p)
            CP_ASYNC_16(rawDstE[p] + add, gsrcE[p] + ko);
    };
    auto issue_B = [&](int c, int st) {
        const uint32_t dbase = sb + SB_O(st) * 4;
        const uint4* sBp = wfn + c * 1024;
#pragma unroll
        for (int q = 0; q < 4; ++q) {
            const int i = tid + q * 256;
            CP_ASYNC_16(dbase + i * 16, sBp + i);
        }
    };
    // nm gathers -> registers (L2-resident, 1-ahead)
    float4 pn[4];
    auto prefetch_nm = [&](int c) {
        const int ko = c * KC;
#pragma unroll
        for (int p = 0; p < 4; ++p)
            pn[p] = *(const float4*)(gsrcN[p] + ko);
    };
    // convert raw eh + nm regs -> bf16 split tiles (SA stage st)
    auto convert = [&](int st) {
        const int sa0 = SA_O(st, 0);
        const int sa1 = SA_O(st, 1);
        const int rwe = RAWE(st);
#pragma unroll
        for (int p = 0; p < 4; ++p) {
            const int row = strow0 + 32 * p;
            const int g = kp ^ (row & 7);
            const float4 e4 = *(const float4*)(smemf + rwe + row * 32 + g * 4);
            float em0 = pn[p].x - fmaxf(e4.x, 0.f);
            float em1 = pn[p].y - fmaxf(e4.y, 0.f);
            float em2 = pn[p].z - fmaxf(e4.z, 0.f);
            float em3 = pn[p].w - fmaxf(e4.w, 0.f);
            float2 bk;
            uint2 s0, s1;
            s0.x = pack_bf2(em0, em1, bk);
            s1.x = pack_bf2n(em0 - bk.x, em1 - bk.y);
            s0.y = pack_bf2(em2, em3, bk);
            s1.y = pack_bf2n(em2 - bk.x, em3 - bk.y);
            const int sw = ((row >> 1) & 3) << 2;
            const int off = row * 16 + ((2 * kp) ^ sw);
            *(uint2*)(smemu + sa0 + off) = s0;
            *(uint2*)(smemu + sa1 + off) = s1;
        }
    };

    // ---- warp tiles: 2 (M) x 4 (N) of 64x32 ----
    const int wm  = (wid >> 2) * 64;
    const int wnb = (wid & 3) * 4;      // nb base (each nb = 8 cols)
    const int wn  = wnb * 8;

    // ldmatrix per-lane geometry
    const int lmrow = lid & 15;
    const int lmkh  = (lid >> 4) << 2;
    uint32_t lmOff[4], lmSw[4];
#pragma unroll
    for (int rbi = 0; rbi < 4; ++rbi) {
        const int row = wm + rbi * 16 + lmrow;
        lmOff[rbi] = row * 16;
        lmSw[rbi]  = ((row >> 1) & 3) << 2;
    }

    float acc[4][4][4];
#pragma unroll
    for (int i = 0; i < 4; ++i)
#pragma unroll
        for (int j = 0; j < 4; ++j)
#pragma unroll
            for (int k = 0; k < 4; ++k) acc[i][j][k] = 0.f;

    // prologue: eh(0)+B(0) as group A, eh(1) as group B; nm(0) in regs
    prefetch_nm(0);
    issue_eh(0, 0);
    issue_B(0, 0);
    CP_ASYNC_COMMIT();
    issue_eh(1, 1);
    CP_ASYNC_COMMIT();

    // chunk schedule (hand-verified group accounting):
    //   top of chunk c: wait_group<=1 forces eh(c) and B(c) complete,
    //   allows eh(c+1) in flight. Last chunk waits for all.
    //   body: convert(c) -> sync -> issue B(c+1), eh(c+2), nm(c+1) -> MMA(c)
    for (int c = 0; c < NCHUNK; ++c) {
        const int st = c & 1;
        if (c == NCHUNK - 1) { CP_ASYNC_WAIT0(); } else { CP_ASYNC_WAIT1(); }
        convert(st);
        __syncthreads();
        if (c + 1 < NCHUNK) {
            issue_B(c + 1, st ^ 1);
            CP_ASYNC_COMMIT();
        }
        if (c + 2 < NCHUNK) {
            issue_eh(c + 2, st);      // rawbuf[st] consumed by convert above
            CP_ASYNC_COMMIT();
        }
        if (c + 1 < NCHUNK) prefetch_nm(c + 1);

        // MMA on stage st (A fragments via ldmatrix.x4)
#pragma unroll
        for (int k16 = 0; k16 < 2; ++k16) {
            uint4 b[4];
#pragma unroll
            for (int nb = 0; nb < 4; ++nb)
                b[nb] = *(const uint4*)(smemu + SB_O(st) +
                         ((k16 * 16 + wnb + nb) * 32 + lid) * 4);
#pragma unroll
            for (int rbi = 0; rbi < 4; ++rbi) {
                const uint32_t idx = (uint32_t)((k16 * 8) | lmkh) ^ lmSw[rbi];
                const uint32_t a0addr =
                    sb + (SA_O(st, 0) + lmOff[rbi] + idx) * 4;
                uint32_t as0[4], as1[4];
                ldmatrix_x4(as0, a0addr);
                ldmatrix_x4(as1, a0addr + 2048 * 4);   // split-lo tile
#pragma unroll
                for (int nb = 0; nb < 4; ++nb)
                    mma_bf16(acc[rbi][nb], as0, b[nb].x, b[nb].y);
#pragma unroll
                for (int nb = 0; nb < 4; ++nb)
                    mma_bf16(acc[rbi][nb], as1, b[nb].x, b[nb].y);
#pragma unroll
                for (int nb = 0; nb < 4; ++nb)
                    mma_bf16(acc[rbi][nb], as0, b[nb].z, b[nb].w);
            }
        }
    }

    // ---- epilogue: ehout = ehin + acc + bias; fused scatter (vector RED) ----
    const int lr4 = lid >> 2;
    const int lm4 = lid & 3;
#pragma unroll
    for (int rbi = 0; rbi < 4; ++rbi) {
#pragma unroll
        for (int half = 0; half < 2; ++half) {
            const int mi = wm + rbi * 16 + half * 8 + lr4;
            const int m = mBase + mi;
            const int d = s_dst[mi];
            const float* ein = ehin + (size_t)m * D_N + nBase;
            float* eout = ehout + (size_t)m * D_N + nBase;
            float* srow = scat + (size_t)d * D_N + nBase;
#pragma unroll
            for (int nb = 0; nb < 4; ++nb) {
                const int cc = wn + nb * 8 + 2 * lm4;
                float2 e = *(const float2*)(ein + cc);
                e.x += acc[rbi][nb][half * 2 + 0] + __ldg(&bias[nBase + cc]);
                e.y += acc[rbi][nb][half * 2 + 1] + __ldg(&bias[nBase + cc + 1]);
                *(float2*)(eout + cc) = e;
                if (do_relu) {
                    red_add_v2(srow + cc, fmaxf(e.x, 0.f), fmaxf(e.y, 0.f));
                } else {
                    red_add_v2(srow + cc, e.x, e.y);
                }
            }
        }
    }
}

// ---------------------------------------------------------------------------
extern "C" void kernel_launch(void* const* d_in, const int* in_sizes, int n_in,
                              void* d_out, int out_size) {
    const float* node_feats = (const float*)d_in[0];
    const float* edge_feats = (const float*)d_in[1];
    const float* Ws         = (const float*)d_in[2];
    const float* bs         = (const float*)d_in[3];
    const int*   edge_index = (const int*)  d_in[4];
    const int*   rev_index  = (const int*)  d_in[5];

    const int* src = edge_index;
    const int* dst = edge_index + E_N;

    float* out_nodes = (float*)d_out;
    float* eh_out    = (float*)d_out + (size_t)V_N * D_N;

    float *eh_scratch = nullptr, *nm0 = nullptr, *nm1 = nullptr, *nm2 = nullptr;
    uint4* wfrag = nullptr;
    cudaGetSymbolAddress((void**)&eh_scratch, g_eh);
    cudaGetSymbolAddress((void**)&nm0, g_nm0);
    cudaGetSymbolAddress((void**)&nm1, g_nm1);
    cudaGetSymbolAddress((void**)&nm2, g_nm2);
    cudaGetSymbolAddress((void**)&wfrag, g_wfrag);

    const int smem_bytes = SMEM_U32 * 4;    // 100352
    cudaFuncSetAttribute(k_gemm_mma,
                         cudaFuncAttributeMaxDynamicSharedMemorySize, smem_bytes);

    const int TPB = 256;
    const int edgeGrid = (E_N * (D_N / 4)) / TPB;   // 80000
    const int nmGrid   = (V_N * (D_N / 4)) / TPB;   // 5000
    dim3 gemmGrid(D_N / TN, E_N / TM);              // (4, 1250)

    // launch order: wfrag(0), zero_all(1), init(2), gemm(3,4,5)
    k_wfrag<<<768, 256>>>(Ws);
    k_zero_all<<<4 * nmGrid, TPB>>>((float4*)nm0, (float4*)nm1,
                                    (float4*)nm2, (float4*)out_nodes);
    k_init_eh_scatter<<<edgeGrid, TPB>>>(node_feats, edge_feats, src, dst, nm0);

    // nm chain: init->nm0; L0 reads nm0, scatters nm1; L1 reads nm1, scatters
    // nm2; L2 reads nm2, scatters out_nodes. eh ping-pong scratch<->d_out.
    float* ehbufs[2] = { eh_scratch, eh_out };
    float* nmchain[4] = { nm0, nm1, nm2, out_nodes };
    const int frag_per_layer = 4 * NCHUNK * 1024;   // uint4 per layer
    for (int l = 0; l < DEPTH_N; ++l) {
        const float* ehin = ehbufs[l & 1];
        float*       eho  = ehbufs[(l + 1) & 1];
        k_gemm_mma<<<gemmGrid, TPB, smem_bytes>>>(
            wfrag + (size_t)l * frag_per_layer, bs + (size_t)l * D_N,
            nmchain[l], ehin, eho, src, rev_index, dst,
            nmchain[l + 1], (l + 1 < DEPTH_N) ? 1 : 0);
    }
}

// round 12
// speedup vs baseline: 1.1144x; 1.1144x over previous
#include <cuda_runtime.h>
#include <cuda_bf16.h>
#include <cstdint>

// ChempropBlock: V=10000 nodes, E=160000 edges, D=512, DEPTH=3
// out = [node_hiddens (V*D) | eh (E*D)] fp32
//
// Per layer l:
//   k_edge_split: em_frag = split_bf16(nm[src] - relu(eh[rev])) written in the
//                 GEMM's fragment tile layout (gather+convert OFF the GEMM path)
//   k_gemm_mma:   streaming 3-stage cp.async pipeline, zero in-loop convert;
//                 eh += em @ W^T + b (in place); epilogue scatters relu(eh)
//                 into nm_next (plain into out_nodes on the last layer).
// GEMM math: mma.sync m16n8k16 bf16, 3-term split (D += A0B0 + A1B0 + A0B1).

#define V_N 10000
#define E_N 160000
#define D_N 512
#define DEPTH_N 3

#define TM 128
#define TN 128
#define KC 32
#define NCHUNK (D_N / KC)     // 16
#define NMB (E_N / TM)        // 1250 m-blocks
#define CH_U32 4096           // u32 per (mblock, chunk) fragment block
#define MB_U32 (NCHUNK * CH_U32)   // 65536 u32 per mblock

__device__ float g_nm0[(size_t)V_N * D_N];
__device__ float g_nm1[(size_t)V_N * D_N];
__device__ float g_nm2[(size_t)V_N * D_N];
// em fragment buffer: [mb(1250)][chunk(16)][sp(2)][row(128)][16 u32] = 327 MB
__device__ uint32_t g_em[(size_t)NMB * MB_U32];
// W fragments: [layer(3)][nblock(4)][chunk(16)][k16(2)][nb(16)][lane(32)] uint4
__device__ uint4 g_wfrag[3 * 4 * 16 * 2 * 16 * 32];

__device__ __forceinline__ uint32_t smem_u32(const void* p) {
    uint32_t a;
    asm("{ .reg .u64 t; cvta.to.shared.u64 t, %1; cvt.u32.u64 %0, t; }"
        : "=r"(a) : "l"(p));
    return a;
}
__device__ __forceinline__ uint32_t pack_bf2(float x, float y, float2& back) {
    __nv_bfloat162 h = __float22bfloat162_rn(make_float2(x, y));
    back = __bfloat1622float2(h);
    return *(uint32_t*)&h;
}
__device__ __forceinline__ uint32_t pack_bf2n(float x, float y) {
    __nv_bfloat162 h = __float22bfloat162_rn(make_float2(x, y));
    return *(uint32_t*)&h;
}
__device__ __forceinline__ void red_add_v4(float* addr, float4 v) {
    asm volatile("red.global.add.v4.f32 [%0], {%1, %2, %3, %4};"
                 :: "l"(addr), "f"(v.x), "f"(v.y), "f"(v.z), "f"(v.w)
                 : "memory");
}
__device__ __forceinline__ void red_add_v2(float* addr, float x, float y) {
    asm volatile("red.global.add.v2.f32 [%0], {%1, %2};"
                 :: "l"(addr), "f"(x), "f"(y)
                 : "memory");
}
__device__ __forceinline__ void ldmatrix_x4(uint32_t* r, uint32_t addr) {
    asm volatile("ldmatrix.sync.aligned.m8n8.x4.shared.b16 {%0,%1,%2,%3}, [%4];"
                 : "=r"(r[0]), "=r"(r[1]), "=r"(r[2]), "=r"(r[3])
                 : "r"(addr));
}
__device__ __forceinline__ void mma_bf16(float* d, const uint32_t* a,
                                         uint32_t b0, uint32_t b1) {
    asm volatile(
        "mma.sync.aligned.m16n8k16.row.col.f32.bf16.bf16.f32 "
        "{%0,%1,%2,%3}, {%4,%5,%6,%7}, {%8,%9}, {%0,%1,%2,%3};"
        : "+f"(d[0]), "+f"(d[1]), "+f"(d[2]), "+f"(d[3])
        : "r"(a[0]), "r"(a[1]), "r"(a[2]), "r"(a[3]), "r"(b0), "r"(b1));
}

#define CP_ASYNC_16(dst_u32, src_ptr) \
    asm volatile("cp.async.cg.shared.global [%0], [%1], 16;" \
                 :: "r"(dst_u32), "l"(src_ptr) : "memory")
#define CP_ASYNC_COMMIT() asm volatile("cp.async.commit_group;" ::: "memory")
#define CP_ASYNC_WAIT0()  asm volatile("cp.async.wait_group 0;" ::: "memory")
#define CP_ASYNC_WAIT1()  asm volatile("cp.async.wait_group 1;" ::: "memory")

// ---------------------------------------------------------------------------
__global__ void k_zero2(float4* __restrict__ a, float4* __restrict__ b) {
    const int n4 = V_N * D_N / 4;
    int i = blockIdx.x * blockDim.x + threadIdx.x;
    if (i < n4) a[i] = make_float4(0.f, 0.f, 0.f, 0.f);
    else        b[i - n4] = make_float4(0.f, 0.f, 0.f, 0.f);
}

// eh0 = nf[src] + ef (written to d_out eh region); relu-scatter eh0 into nm
__global__ void k_init_eh_scatter(const float* __restrict__ nf,
                                  const float* __restrict__ ef,
                                  const int* __restrict__ src,
                                  const int* __restrict__ dst,
                                  float* __restrict__ eh,
                                  float* __restrict__ nm) {
    int idx = blockIdx.x * blockDim.x + threadIdx.x;   // < E*D/4
    int e = idx >> 7;
    int c = (idx & 127) << 2;
    int s = __ldg(&src[e]);
    const float4 a = *(const float4*)(nf + (size_t)s * D_N + c);
    const float4 b = *(const float4*)(ef + (size_t)e * D_N + c);
    float4 r; r.x = a.x + b.x; r.y = a.y + b.y; r.z = a.z + b.z; r.w = a.w + b.w;
    *(float4*)(eh + (size_t)e * D_N + c) = r;
    int d = __ldg(&dst[e]);
    float4 rr;
    rr.x = fmaxf(r.x, 0.f); rr.y = fmaxf(r.y, 0.f);
    rr.z = fmaxf(r.z, 0.f); rr.w = fmaxf(r.w, 0.f);
    red_add_v4(nm + (size_t)d * D_N + c, rr);
}

// Precompute bf16-split W fragments (m16n8k16 B operand layout, row.col).
__global__ void k_wfrag(const float* __restrict__ Ws) {
    int t = blockIdx.x * blockDim.x + threadIdx.x;     // < 196608
    int lane  = t & 31;
    int nb    = (t >> 5) & 15;
    int k16   = (t >> 9) & 1;
    int chunk = (t >> 10) & 15;
    int nblk  = (t >> 14) & 3;
    int layer = t >> 16;
    int n = nblk * 128 + nb * 8 + (lane >> 2);
    int k = chunk * 32 + k16 * 16 + (lane & 3) * 2;
    const float* w = Ws + ((size_t)layer * D_N + n) * D_N + k;
    float w00 = w[0], w01 = w[1], w10 = w[8], w11 = w[9];
    float2 bk;
    uint4 o;
    o.x = pack_bf2(w00, w01, bk);
    o.z = pack_bf2n(w00 - bk.x, w01 - bk.y);
    o.y = pack_bf2(w10, w11, bk);
    o.w = pack_bf2n(w10 - bk.x, w11 - bk.y);
    g_wfrag[t] = o;
}

// ---------------------------------------------------------------------------
// em_frag writer: for each edge row m and 16B-granule kp (8 per row),
// compute em = nm[src[m]] - relu(eh[rev[m]]) over all 16 chunks and store the
// bf16 split pair in fragment layout:
//   u32 addr = mb*MB_U32 + chunk*CH_U32 + sp*2048 + ri*16 + ((2*kp) ^ sw(ri))
// (identical layout + math to the old in-GEMM convert).
// ---------------------------------------------------------------------------
__global__ void k_edge_split(const float* __restrict__ nm,
                             const float* __restrict__ eh,
                             const int* __restrict__ src,
                             const int* __restrict__ rev) {
    int g = blockIdx.x * blockDim.x + threadIdx.x;   // < E*8
    int row = g >> 3;
    int kp  = g & 7;
    int s = __ldg(&src[row]);
    int r = __ldg(&rev[row]);
    const float* nrow = nm + (size_t)s * D_N + kp * 4;
    const float* erow = eh + (size_t)r * D_N + kp * 4;
    const int mb = row >> 7;
    const int ri = row & 127;
    const int sw = ((ri >> 1) & 3) << 2;
    uint32_t* base = g_em + (size_t)mb * MB_U32 + ri * 16 + ((2 * kp) ^ sw);
#pragma unroll 4
    for (int c = 0; c < NCHUNK; ++c) {
        const float4 n4 = *(const float4*)(nrow + c * KC);
        const float4 e4 = *(const float4*)(erow + c * KC);
        float em0 = n4.x - fmaxf(e4.x, 0.f);
        float em1 = n4.y - fmaxf(e4.y, 0.f);
        float em2 = n4.z - fmaxf(e4.z, 0.f);
        float em3 = n4.w - fmaxf(e4.w, 0.f);
        float2 bk;
        uint2 s0, s1;
        s0.x = pack_bf2(em0, em1, bk);
        s1.x = pack_bf2n(em0 - bk.x, em1 - bk.y);
        s0.y = pack_bf2(em2, em3, bk);
        s1.y = pack_bf2n(em2 - bk.x, em3 - bk.y);
        *(uint2*)(base + c * CH_U32)        = s0;   // split-hi (sp=0)
        *(uint2*)(base + c * CH_U32 + 2048) = s1;   // split-lo (sp=1)
    }
}

// ---------------------------------------------------------------------------
// Streaming GEMM. smem (b32): [0..511] s_dst + pad; 3 stages of 8192:
//   stage: SA = [sp(2)][row(128)][16 u32] (4096), SB = [k16][nb][lane] uint4 (4096)
// total 25088 u32 = 100352 B -> 2 CTA/SM.
// ---------------------------------------------------------------------------
#define STG_U32 8192
#define SMEM_U32 (512 + 3 * STG_U32)   // 25088

__global__ void __launch_bounds__(256, 2)
k_gemm_mma(const uint4* __restrict__ wf,       // this layer's W fragment table
           const float* __restrict__ bias,
           const uint32_t* __restrict__ em,
           float* __restrict__ eh,             // in-place update
           const int* __restrict__ dst,
           float* __restrict__ scat,
           int do_relu) {
    extern __shared__ float smemf[];
    uint32_t* smemu = (uint32_t*)smemf;
    int* s_dst = (int*)smemf;

    const int tid = threadIdx.x;
    const int wid = tid >> 5;
    const int lid = tid & 31;
    const int mBase = blockIdx.y * TM;
    const int nBase = blockIdx.x * TN;
    const uint32_t* emb = em + (size_t)blockIdx.y * MB_U32;
    const uint4* wfn = wf + (size_t)blockIdx.x * (NCHUNK * 1024);

    if (tid < TM) s_dst[tid] = __ldg(&dst[mBase + tid]);
    // no barrier needed here: s_dst is read only in the epilogue, long after
    // the pipeline's __syncthreads.

    const uint32_t sb = smem_u32(smemf);

    auto issue = [&](int c, int stg) {
        const uint32_t ab = sb + (512 + stg * STG_U32) * 4;
        const uint32_t* gA = emb + c * CH_U32;
#pragma unroll
        for (int q = 0; q < 4; ++q) {
            const int i = tid + q * 256;
            CP_ASYNC_16(ab + i * 16, gA + i * 4);
        }
        const uint32_t bb = ab + 4096 * 4;
        const uint4* gB = wfn + c * 1024;
#pragma unroll
        for (int q = 0; q < 4; ++q) {
            const int i = tid + q * 256;
            CP_ASYNC_16(bb + i * 16, gB + i);
        }
    };

    // ---- warp tiles: 2 (M) x 4 (N) of 64x32 ----
    const int wm  = (wid >> 2) * 64;
    const int wnb = (wid & 3) * 4;
    const int wn  = wnb * 8;

    const int lmrow = lid & 15;
    const int lmkh  = (lid >> 4) << 2;
    uint32_t lmOff[4], lmSw[4];
#pragma unroll
    for (int rbi = 0; rbi < 4; ++rbi) {
        const int row = wm + rbi * 16 + lmrow;
        lmOff[rbi] = row * 16;
        lmSw[rbi]  = ((row >> 1) & 3) << 2;
    }

    float acc[4][4][4];
#pragma unroll
    for (int i = 0; i < 4; ++i)
#pragma unroll
        for (int j = 0; j < 4; ++j)
#pragma unroll
            for (int k = 0; k < 4; ++k) acc[i][j][k] = 0.f;

    // 3-stage pipeline: issue(0),(1) up front; per chunk:
    //   wait (<=1, last chunk 0) -> barrier -> issue(c+2) -> MMA(c)
    // stage (c+2)%3 was read by MMA(c-1), complete in all warps before this
    // barrier, so overwrite is safe; issue-before-MMA gives ~2 MMA phases of
    // latency cover for the streaming copies.
    issue(0, 0); CP_ASYNC_COMMIT();
    issue(1, 1); CP_ASYNC_COMMIT();

    for (int c = 0; c < NCHUNK; ++c) {
        const int stg = c % 3;
        if (c == NCHUNK - 1) { CP_ASYNC_WAIT0(); } else { CP_ASYNC_WAIT1(); }
        __syncthreads();
        if (c + 2 < NCHUNK) {
            issue(c + 2, (c + 2) % 3);
            CP_ASYNC_COMMIT();
        }

        const uint32_t sa_base = 512 + stg * STG_U32;        // u32 index
        const uint32_t sb_base = sa_base + 4096;
#pragma unroll
        for (int k16 = 0; k16 < 2; ++k16) {
            uint4 b[4];
#pragma unroll
            for (int nb = 0; nb < 4; ++nb)
                b[nb] = *(const uint4*)(smemu + sb_base +
                         ((k16 * 16 + wnb + nb) * 32 + lid) * 4);
#pragma unroll
            for (int rbi = 0; rbi < 4; ++rbi) {
                const uint32_t idx = (uint32_t)((k16 * 8) | lmkh) ^ lmSw[rbi];
                const uint32_t a0addr = sb + (sa_base + lmOff[rbi] + idx) * 4;
                uint32_t as0[4], as1[4];
                ldmatrix_x4(as0, a0addr);
                ldmatrix_x4(as1, a0addr + 2048 * 4);   // split-lo
#pragma unroll
                for (int nb = 0; nb < 4; ++nb)
                    mma_bf16(acc[rbi][nb], as0, b[nb].x, b[nb].y);
#pragma unroll
                for (int nb = 0; nb < 4; ++nb)
                    mma_bf16(acc[rbi][nb], as1, b[nb].x, b[nb].y);
#pragma unroll
                for (int nb = 0; nb < 4; ++nb)
                    mma_bf16(acc[rbi][nb], as0, b[nb].z, b[nb].w);
            }
        }
    }

    // ---- epilogue: eh += acc + bias (in place); fused scatter ----
    const int lr4 = lid >> 2;
    const int lm4 = lid & 3;
#pragma unroll
    for (int rbi = 0; rbi < 4; ++rbi) {
#pragma unroll
        for (int half = 0; half < 2; ++half) {
            const int mi = wm + rbi * 16 + half * 8 + lr4;
            const int m = mBase + mi;
            const int d = s_dst[mi];
            float* erow = eh + (size_t)m * D_N + nBase;
            float* srow = scat + (size_t)d * D_N + nBase;
#pragma unroll
            for (int nb = 0; nb < 4; ++nb) {
                const int cc = wn + nb * 8 + 2 * lm4;
                float2 e = *(const float2*)(erow + cc);
                e.x += acc[rbi][nb][half * 2 + 0] + __ldg(&bias[nBase + cc]);
                e.y += acc[rbi][nb][half * 2 + 1] + __ldg(&bias[nBase + cc + 1]);
                *(float2*)(erow + cc) = e;
                if (do_relu) {
                    red_add_v2(srow + cc, fmaxf(e.x, 0.f), fmaxf(e.y, 0.f));
                } else {
                    red_add_v2(srow + cc, e.x, e.y);
                }
            }
        }
    }
}

// ---------------------------------------------------------------------------
extern "C" void kernel_launch(void* const* d_in, const int* in_sizes, int n_in,
                              void* d_out, int out_size) {
    const float* node_feats = (const float*)d_in[0];
    const float* edge_feats = (const float*)d_in[1];
    const float* Ws         = (const float*)d_in[2];
    const float* bs         = (const float*)d_in[3];
    const int*   edge_index = (const int*)  d_in[4];
    const int*   rev_index  = (const int*)  d_in[5];

    const int* src = edge_index;
    const int* dst = edge_index + E_N;

    float* out_nodes = (float*)d_out;
    float* eh        = (float*)d_out + (size_t)V_N * D_N;   // lives here; in-place

    float *nm0 = nullptr, *nm1 = nullptr, *nm2 = nullptr;
    uint32_t* em = nullptr;
    uint4* wfrag = nullptr;
    cudaGetSymbolAddress((void**)&nm0, g_nm0);
    cudaGetSymbolAddress((void**)&nm1, g_nm1);
    cudaGetSymbolAddress((void**)&nm2, g_nm2);
    cudaGetSymbolAddress((void**)&em, g_em);
    cudaGetSymbolAddress((void**)&wfrag, g_wfrag);

    const int smem_bytes = SMEM_U32 * 4;    // 100352
    cudaFuncSetAttribute(k_gemm_mma,
                         cudaFuncAttributeMaxDynamicSharedMemorySize, smem_bytes);

    const int TPB = 256;
    const int edgeGrid  = (E_N * (D_N / 4)) / TPB;      // 80000
    const int zeroGrid  = (2 * V_N * (D_N / 4)) / TPB;  // 10000 (2 buffers)
    const int splitGrid = (E_N * 8) / TPB;              // 5000
    dim3 gemmGrid(D_N / TN, E_N / TM);                  // (4, 1250)

    // launches: 0 wfrag, 1 zero(nm0,nm1), 2 zero(nm2,out), 3 init,
    //           4 split0, 5 gemm0 <- ncu -s 5 captures gemm0
    k_wfrag<<<768, 256>>>(Ws);
    k_zero2<<<zeroGrid, TPB>>>((float4*)nm0, (float4*)nm1);
    k_zero2<<<zeroGrid, TPB>>>((float4*)nm2, (float4*)out_nodes);
    k_init_eh_scatter<<<edgeGrid, TPB>>>(node_feats, edge_feats, src, dst,
                                         eh, nm0);

    float* nmchain[4] = { nm0, nm1, nm2, out_nodes };
    const int frag_per_layer = 4 * NCHUNK * 1024;   // uint4 per layer
    for (int l = 0; l < DEPTH_N; ++l) {
        k_edge_split<<<splitGrid, TPB>>>(nmchain[l], eh, src, rev_index);
        k_gemm_mma<<<gemmGrid, TPB, smem_bytes>>>(
            wfrag + (size_t)l * frag_per_layer, bs + (size_t)l * D_N,
            em, eh, dst, nmchain[l + 1], (l + 1 < DEPTH_N) ? 1 : 0);
    }
}